// round 6
// baseline (speedup 1.0000x reference)
#include <cuda_runtime.h>
#include <math_constants.h>

// Causal sliding-window min, W = 128 == segment size (van Herk / Gil-Werman).
// out[seg g, p] = min(pref_g[p], suf_{g-1}[p+1]),  suf[128] := +inf.
//
// Warp-per-segment, 4 elems/lane, SEGW contiguous segments per warp plus a
// redundantly loaded halo segment (suffix only). Register-resident suffix
// handoff: lane l needs suf_prev at 4l+1..4l+4 = {ps1,ps2,ps3,psc}.
// One 5-step shfl_xor butterfly gives both directional scans.
// Loads run through a depth-4 ring buffer (software pipeline) to keep
// register pressure low while still covering L2 latency.

#define WSZ     128
#define NWARPS  4
#define BLOCK   (NWARPS * 32)     // 128 threads
#define SEGW    8                 // segments per warp
#define SEGS    (NWARPS * SEGW)   // 32 segments per CTA
#define TILE    (SEGS * WSZ)      // 4096 elements per CTA
#define PIPE    4                 // load pipeline depth

__device__ __forceinline__ float4 ld_guard(const float* __restrict__ x,
                                           int base, int n)
{
    const float INF = CUDART_INF_F;
    float4 v;
    v.x = (base >= 0 && base + 0 < n) ? x[base + 0] : INF;
    v.y = (base >= 0 && base + 1 < n) ? x[base + 1] : INF;
    v.z = (base >= 0 && base + 2 < n) ? x[base + 2] : INF;
    v.w = (base >= 0 && base + 3 < n) ? x[base + 3] : INF;
    return v;
}

template<bool SAFE>
__device__ __forceinline__ void run_warp(const float* __restrict__ x,
                                         float* __restrict__ out,
                                         int wbase, int n, int lane)
{
    const float INF = CUDART_INF_F;

    // halo + first PIPE-1 segment loads in flight
    float4 vh = SAFE ? *(const float4*)(x + (wbase - WSZ))
                     : ld_guard(x, wbase - WSZ, n);
    float4 vbuf[PIPE];
    #pragma unroll
    for (int k = 0; k < PIPE - 1; k++)
        vbuf[k] = SAFE ? *(const float4*)(x + (wbase + k * WSZ))
                       : ld_guard(x, wbase + k * WSZ, n);

    // ---- halo: suffix handoff registers ----
    float ps1, ps2, ps3, psc;
    {
        float s2 = fminf(vh.z, vh.w);
        float s1 = fminf(vh.y, s2);
        float s0 = fminf(vh.x, s1);
        float B = s0, A = s0;                // backward-only butterfly
        #pragma unroll
        for (int d = 1; d < 32; d <<= 1) {
            float Ap = __shfl_xor_sync(0xffffffffu, A, d);
            if (!(lane & d)) B = fminf(B, Ap);
            A = fminf(A, Ap);
        }
        float sc = __shfl_down_sync(0xffffffffu, B, 1);
        if (lane == 31) sc = INF;
        ps1 = fminf(s1, sc);
        ps2 = fminf(s2, sc);
        ps3 = fminf(vh.w, sc);
        psc = sc;
    }

    // ---- main segments, pipelined loads ----
    #pragma unroll
    for (int k = 0; k < SEGW; k++) {
        if (k + PIPE - 1 < SEGW) {
            int lb = wbase + (k + PIPE - 1) * WSZ;
            vbuf[(k + PIPE - 1) % PIPE] =
                SAFE ? *(const float4*)(x + lb) : ld_guard(x, lb, n);
        }
        const float4 v = vbuf[k % PIPE];

        // local prefix + suffix chains
        float p1 = fminf(v.y, v.x);
        float p2 = fminf(v.z, p1);
        float p3 = fminf(v.w, p2);
        float s2 = fminf(v.z, v.w);
        float s1 = fminf(v.y, s2);
        float s0 = fminf(v.x, s1);           // lane min

        // bidirectional butterfly over lane mins
        float F = s0, B = s0, A = s0;
        #pragma unroll
        for (int d = 1; d < 32; d <<= 1) {
            float Ap = __shfl_xor_sync(0xffffffffu, A, d);
            if (lane & d) F = fminf(F, Ap);
            else          B = fminf(B, Ap);
            A = fminf(A, Ap);
        }
        float pc = __shfl_up_sync(0xffffffffu, F, 1);    // excl prefix carry
        if (lane == 0) pc = INF;
        float sc = __shfl_down_sync(0xffffffffu, B, 1);  // excl suffix carry
        if (lane == 31) sc = INF;

        // combine with previous-segment suffix (registers)
        float e0 = fminf(fminf(v.x, pc), ps1);
        float e1 = fminf(fminf(p1,  pc), ps2);
        float e2 = fminf(fminf(p2,  pc), ps3);
        float e3 = fminf(fminf(p3,  pc), psc);

        int base = wbase + k * WSZ;
        if (SAFE) {
            __stcs((float4*)(out + base), make_float4(e0, e1, e2, e3));
        } else {
            if (base + 0 < n && base >= 0) out[base + 0] = e0;
            if (base + 1 < n && base >= 0) out[base + 1] = e1;
            if (base + 2 < n && base >= 0) out[base + 2] = e2;
            if (base + 3 < n && base >= 0) out[base + 3] = e3;
        }

        // suffix handoff to next segment
        ps1 = fminf(s1, sc);
        ps2 = fminf(s2, sc);
        ps3 = fminf(v.w, sc);
        psc = sc;
    }
}

__global__ __launch_bounds__(BLOCK)
void swmin128_kernel(const float* __restrict__ x,
                     float* __restrict__ out,
                     int n)
{
    const int lane = threadIdx.x & 31;
    const int wid  = threadIdx.x >> 5;
    const int wseg  = blockIdx.x * SEGS + wid * SEGW;  // first segment of warp
    const int wbase = wseg * WSZ + lane * 4;

    // warp-uniform safety: halo in-bounds below, all SEGW segments below n
    const bool safe = (wseg >= 1) && ((wseg + SEGW) * WSZ <= n);
    if (safe) run_warp<true >(x, out, wbase, n, lane);
    else      run_warp<false>(x, out, wbase, n, lane);
}

extern "C" void kernel_launch(void* const* d_in, const int* in_sizes, int n_in,
                              void* d_out, int out_size)
{
    const float* x = (const float*)d_in[0];
    float* out = (float*)d_out;
    int n = in_sizes[0];
    int grid = (n + TILE - 1) / TILE;   // 2048 for N = 8,388,608
    swmin128_kernel<<<grid, BLOCK>>>(x, out, n);
}